// round 12
// baseline (speedup 1.0000x reference)
#include <cuda_runtime.h>

// Problem constants
#define BB 2
#define CC 64
#define HH 64
#define WW 128
#define HWN (HH*WW)         // 8192
#define NXG 512
#define NYG 512
#define NCELL (NXG*NYG)     // 262144
#define SCH 32              // near-chunk slots (dynamic count may use fewer)
#define NCHUNK 256
#define MAXSLOT 16384       // max touched cells per batch (8192 near + 8192 far)
#define POS_INF (3.402823466e38f)
#define IDX_INF 0x7fffffff

// init_kernel: zero g_cnt (131072 float4) + g_acc (524288 float4)
#define F4_CNT (BB*NCELL/4)
#define F4_ACC (BB*MAXSLOT*CC/4)
#define INIT_BLKS ((F4_CNT + F4_ACC) / (256*4))   // 640

// prep_kernel block-range dispatch: compact first (long pole), then transpose
#define CP_BLKS   BB
#define TR_BLKS   1024      // (HWN/32) * (CC/32) * BB
#define PREP_BLKS (CP_BLKS + TR_BLKS)

// Scratch (device globals — no runtime allocation allowed)
__device__ float  g_fvT[BB*HWN*CC];          // transposed features (B, HW, C)
__device__ float4 g_nearc[BB*HWN];           // compacted valid near pts {x,y,z,|n|^2}
__device__ int    g_near_idx[BB*HWN];        // original index of compacted near pts
__device__ int    g_near_cnt[BB];
__device__ int    g_far_idx[BB*HWN];         // compacted valid+in-range far point indices
__device__ int    g_far_cnt[BB];
__device__ float4 g_ps[BB*SCH*HWN];          // partial top-3 d2 {s0,s1,s2,-} [b][chunk][slot]
__device__ int4   g_pi[BB*SCH*HWN];          // partial top-3 compacted idx {i0,i1,i2,-}
__device__ float  g_cnt[BB*NCELL];           // per-cell point counts (zeroed per call)
__device__ int    g_slot[BB*NCELL];          // cell -> compact slot (valid iff cnt>0)
__device__ int    g_nslot[BB];               // slot allocator
__device__ float  g_acc[BB*MAXSLOT*CC];      // compact per-slot channel sums (zeroed)

// Sorted-insert of smallest-3, strict '<' so earlier indices win ties
#define INS(val, jj) do {                                             \
    if ((val) < s2) {                                                 \
        if ((val) < s1) {                                             \
            s2 = s1; i2 = i1;                                         \
            if ((val) < s0) { s1 = s0; i1 = i0; s0 = (val); i0 = (jj); } \
            else            { s1 = (val); i1 = (jj); }                \
        } else { s2 = (val); i2 = (jj); }                             \
    }                                                                 \
} while (0)

__device__ __forceinline__ int cell_x(float x) { return (int)floorf(__fdiv_rn(x, 0.1f)); }
__device__ __forceinline__ int cell_y(float y) { return (int)floorf(__fdiv_rn(__fsub_rn(y, -25.6f), 0.1f)); }

// |p|^2 with the reference's rounding: ((x*x + y*y) + z*z), no fma contraction
__device__ __forceinline__ float sqnorm_ref(float x, float y, float z) {
    return __fadd_rn(__fadd_rn(__fmul_rn(x, x), __fmul_rn(y, y)), __fmul_rn(z, z));
}

// GEMM-replica pair distance: acc = rn(a0*b0); acc = fma(a1,b1,acc); acc = fma(a2,b2,acc);
// d2 = rn( rn(fsq+nsq) - acc ).  Pre-doubled f is bit-equal to the alpha=2 folded GEMM.
__device__ __forceinline__ float d2_ref(float fx2, float fy2, float fz2, float fsq,
                                        float nx, float ny, float nz, float nsq) {
    float acc = __fmul_rn(fx2, nx);
    acc = __fmaf_rn(fy2, ny, acc);
    acc = __fmaf_rn(fz2, nz, acc);
    return __fsub_rn(__fadd_rn(fsq, nsq), acc);
}

// ---------------------------------------------------------------------------
// 0. init: zero g_cnt + g_acc + g_nslot (10 MB total). Separate launch —
//    prep's counting atomics must not race with zeroing.
// ---------------------------------------------------------------------------
__global__ void __launch_bounds__(256) init_kernel() {
    size_t i0 = (size_t)blockIdx.x * 1024 + threadIdx.x;
    const float4 z = make_float4(0.f, 0.f, 0.f, 0.f);
    #pragma unroll
    for (int k = 0; k < 4; k++) {
        size_t i = i0 + (size_t)k * 256;
        if (i < F4_CNT) ((float4*)g_cnt)[i] = z;
        else            ((float4*)g_acc)[i - F4_CNT] = z;
    }
    if (blockIdx.x == 0 && threadIdx.x < BB) g_nslot[threadIdx.x] = 0;
}

// ---------------------------------------------------------------------------
// 1. prep: compact (+count +slot-alloc) at bid 0..1, transpose at bid 2..1025
// ---------------------------------------------------------------------------
__global__ void __launch_bounds__(256) prep_kernel(const float* __restrict__ fv,
                                                   const float* __restrict__ pif,
                                                   const int*   __restrict__ mask,
                                                   const float* __restrict__ piff,
                                                   const int*   __restrict__ maskf) {
    int bid = blockIdx.x;
    int tid = threadIdx.x;

    if (bid >= CP_BLKS) {                        // ---- transpose ----
        bid -= CP_BLKS;
        __shared__ float tile[32][33];
        int b  = bid / ((HWN/32) * (CC/32));
        int r  = bid % ((HWN/32) * (CC/32));
        int c0 = (r / (HWN/32)) * 32;
        int p0 = (r % (HWN/32)) * 32;
        int tx = tid & 31, ty = tid >> 5;        // 32 x 8
        #pragma unroll
        for (int i = ty; i < 32; i += 8)
            tile[i][tx] = fv[((size_t)b*CC + c0 + i) * HWN + p0 + tx];
        __syncthreads();
        #pragma unroll
        for (int i = ty; i < 32; i += 8)
            g_fvT[((size_t)b*HWN + p0 + i) * CC + c0 + tx] = tile[tx][i];
        return;
    }

    // ---- compaction + counting + slot allocation (1 block per batch) ----
    int b = bid;
    int warp = tid >> 5, lane = tid & 31;
    __shared__ unsigned smask[256];              // validity masks, index-ordered chunks
    __shared__ int sscan[256];                   // inclusive scan of popcounts

    // ===== phase A: near (compaction predicate = mask > 0) =====
    const int*   mn = mask + b * HWN;
    const float* pn = pif + (size_t)b * 4 * HWN;
    #pragma unroll 4
    for (int r = 0; r < 32; r++) {
        int p = r * 256 + tid;                   // coalesced
        unsigned m = __ballot_sync(0xffffffffu, mn[p] > 0);
        if (lane == 0) smask[r*8 + warp] = m;    // chunk key = p/32
    }
    __syncthreads();
    sscan[tid] = __popc(smask[tid]);
    __syncthreads();
    #pragma unroll
    for (int off = 1; off < 256; off <<= 1) {
        int v = (tid >= off) ? sscan[tid - off] : 0;
        __syncthreads();
        sscan[tid] += v;
        __syncthreads();
    }
    if (tid == 255) g_near_cnt[b] = sscan[255];
    #pragma unroll 4
    for (int r = 0; r < 32; r++) {
        int p = r * 256 + tid;
        if (mn[p] > 0) {
            int key = r*8 + warp;
            unsigned m = smask[key];
            int rank = sscan[key] - __popc(m) + __popc(m & ((1u << lane) - 1u));
            float x = pn[p], y = pn[HWN + p], z = pn[2*HWN + p];
            g_nearc[b*HWN + rank] = make_float4(x, y, z, sqnorm_ref(x, y, z));
            g_near_idx[b*HWN + rank] = p;
            // count + slot-alloc for valid near point landing in the BEV grid
            int ix = cell_x(x), iy = cell_y(y);
            if (ix >= 0 && ix < NXG && iy >= 0 && iy < NYG) {
                int cell = b*NCELL + iy*NXG + ix;
                float old = atomicAdd(&g_cnt[cell], 1.0f);
                if (old == 0.0f)
                    g_slot[cell] = atomicAdd(&g_nslot[b], 1);
            }
        }
    }
    __syncthreads();

    // ===== phase B: far (predicate = mask > 0 && cell in range) =====
    const int*   mf  = maskf + b * HWN;
    const float* pff = piff + (size_t)b * 4 * HWN;
    #pragma unroll 4
    for (int r = 0; r < 32; r++) {
        int p = r * 256 + tid;
        bool v = mf[p] > 0;
        if (v) {
            int ix = cell_x(pff[p]), iy = cell_y(pff[HWN + p]);
            v = (ix >= 0 && ix < NXG && iy >= 0 && iy < NYG);
        }
        unsigned m = __ballot_sync(0xffffffffu, v);
        if (lane == 0) smask[r*8 + warp] = m;
    }
    __syncthreads();
    sscan[tid] = __popc(smask[tid]);
    __syncthreads();
    #pragma unroll
    for (int off = 1; off < 256; off <<= 1) {
        int v = (tid >= off) ? sscan[tid - off] : 0;
        __syncthreads();
        sscan[tid] += v;
        __syncthreads();
    }
    if (tid == 255) g_far_cnt[b] = sscan[255];
    #pragma unroll 4
    for (int r = 0; r < 32; r++) {
        int p = r * 256 + tid;
        int key = r*8 + warp;
        unsigned m = smask[key];
        if ((m >> lane) & 1u) {
            int rank = sscan[key] - __popc(m) + __popc(m & ((1u << lane) - 1u));
            g_far_idx[b*HWN + rank] = p;
            int ix = cell_x(pff[p]), iy = cell_y(pff[HWN + p]);
            int cell = b*NCELL + iy*NXG + ix;
            float old = atomicAdd(&g_cnt[cell], 1.0f);
            if (old == 0.0f)
                g_slot[cell] = atomicAdd(&g_nslot[b], 1);
        }
    }
}

// ---------------------------------------------------------------------------
// 2. kNN over compacted near points: thread = far point, small smem chunk
// ---------------------------------------------------------------------------
__global__ void __launch_bounds__(256) knn_kernel(const float* __restrict__ pif_far) {
    __shared__ float4 sh[NCHUNK];
    int b  = blockIdx.z;
    int ch = blockIdx.y;
    int nbase = ch * NCHUNK;
    int ncnt = g_near_cnt[b];
    if (nbase >= ncnt) return;
    if (blockIdx.x * 256 >= g_far_cnt[b]) return;

    int navail = min(NCHUNK, ncnt - nbase);
    int n8 = (navail + 7) & ~7;                  // pad to multiple of 8
    const float4* src = g_nearc + b*HWN + nbase;
    for (int i = threadIdx.x; i < n8; i += 256)
        sh[i] = (i < navail) ? src[i] : make_float4(0.f, 0.f, 0.f, 1e30f);
    __syncthreads();

    int slot = blockIdx.x * 256 + threadIdx.x;
    if (slot >= g_far_cnt[b]) return;
    int p = g_far_idx[b*HWN + slot];

    const float* pf = pif_far + (size_t)b * 4 * HWN;
    float x = pf[p], y = pf[HWN + p], z = pf[2*HWN + p];
    float fsq = sqnorm_ref(x, y, z);
    float fx2 = 2.0f * x, fy2 = 2.0f * y, fz2 = 2.0f * z;  // exact

    float s0 = POS_INF, s1 = POS_INF, s2 = POS_INF;
    int   i0 = 0, i1 = 0, i2 = 0;

    #pragma unroll 1
    for (int j = 0; j < n8; j += 8) {
        float d[8];
        #pragma unroll
        for (int u = 0; u < 8; u++) {
            float4 q = sh[j + u];
            d[u] = d2_ref(fx2, fy2, fz2, fsq, q.x, q.y, q.z, q.w);
        }
        float m = fminf(fminf(fminf(d[0], d[1]), fminf(d[2], d[3])),
                        fminf(fminf(d[4], d[5]), fminf(d[6], d[7])));
        if (m < s2) {   // rarely taken
            #pragma unroll
            for (int u = 0; u < 8; u++) INS(d[u], nbase + j + u);
        }
    }

    int base = (b*SCH + ch) * HWN + slot;
    g_ps[base] = make_float4(s0, s1, s2, 0.0f);
    g_pi[base] = make_int4(i0, i1, i2, 0);
}

// ---------------------------------------------------------------------------
// 3. fused scatter into COMPACT accumulator (L2-resident atomics).
//    blockIdx.z = 0: near points (64 lanes/pt).
//    blockIdx.z = 1: far points — warp-parallel top-3 merge, IDW weights
//    (reference rounding), then 64-lane gather+accumulate.
// ---------------------------------------------------------------------------
__global__ void __launch_bounds__(256) scatter_kernel(const float* __restrict__ pif_far) {
    int b = blockIdx.y;
    int local = threadIdx.x >> 6;                // point-in-block 0..3
    int lane64 = threadIdx.x & 63;
    int slot = blockIdx.x * 4 + local;

    if (blockIdx.z == 0) {
        if (slot >= g_near_cnt[b]) return;
        float4 q = g_nearc[b*HWN + slot];
        int ix = cell_x(q.x), iy = cell_y(q.y);
        if (ix < 0 || ix >= NXG || iy < 0 || iy >= NYG) return;
        int sl = g_slot[b*NCELL + iy*NXG + ix];
        int p = g_near_idx[b*HWN + slot];
        float f = g_fvT[((size_t)b*HWN + p) * CC + lane64];   // coalesced
        atomicAdd(g_acc + ((size_t)(b*MAXSLOT + sl))*CC + lane64, f);
        return;
    }

    // ---- far path ----
    __shared__ float sw[4][3];
    __shared__ int   si[4][3];
    __shared__ int   sslot[4];

    int fcnt = g_far_cnt[b];
    bool active = slot < fcnt;
    int half = lane64 >> 5;                      // warp-half within the point
    int lane = lane64 & 31;                      // chunk id for half 0

    if (active && half == 0) {
        // lane = chunk; load this chunk's sorted top-3 partial (or sentinels)
        int ncnt = g_near_cnt[b];
        float a0 = POS_INF, a1 = POS_INF, a2 = POS_INF;
        int   c0 = IDX_INF,  c1 = IDX_INF,  c2 = IDX_INF;
        if (lane * NCHUNK < ncnt) {
            int base = (b*SCH + lane) * HWN + slot;
            float4 v = g_ps[base];
            int4  iv = g_pi[base];
            a0 = v.x; a1 = v.y; a2 = v.z;
            c0 = iv.x; c1 = iv.y; c2 = iv.z;
        }
        // 3-round warp argmin by (value, then compacted index) — identical to
        // sequential INS order (chunks partition ascending indices; within-chunk
        // triples are index-ordered on equal values).
        float S[3]; int I[3];
        #pragma unroll
        for (int k = 0; k < 3; k++) {
            float bv = a0; int bx = c0;
            #pragma unroll
            for (int off = 16; off; off >>= 1) {
                float ov = __shfl_down_sync(0xffffffffu, bv, off);
                int   ox = __shfl_down_sync(0xffffffffu, bx, off);
                if (ov < bv || (ov == bv && ox < bx)) { bv = ov; bx = ox; }
            }
            bv = __shfl_sync(0xffffffffu, bv, 0);
            bx = __shfl_sync(0xffffffffu, bx, 0);
            S[k] = bv; I[k] = bx;
            if (c0 == bx) {                      // unique index -> unique winner
                a0 = a1; c0 = c1; a1 = a2; c1 = c2;
                a2 = POS_INF; c2 = IDX_INF;
            }
        }
        if (lane == 0) {
            // IDW weights exactly as reference: r = 1/(d+1e-8); w = r/((r0+r1)+r2)
            float r0 = __fdiv_rn(1.0f, __fadd_rn(S[0], 1e-8f));
            float r1 = __fdiv_rn(1.0f, __fadd_rn(S[1], 1e-8f));
            float r2 = __fdiv_rn(1.0f, __fadd_rn(S[2], 1e-8f));
            float rs = __fadd_rn(__fadd_rn(r0, r1), r2);
            sw[local][0] = __fdiv_rn(r0, rs);
            sw[local][1] = __fdiv_rn(r1, rs);
            sw[local][2] = __fdiv_rn(r2, rs);
            si[local][0] = g_near_idx[b*HWN + I[0]];
            si[local][1] = g_near_idx[b*HWN + I[1]];
            si[local][2] = g_near_idx[b*HWN + I[2]];
            int p = g_far_idx[b*HWN + slot];
            const float* pf = pif_far + (size_t)b * 4 * HWN;
            int ix = cell_x(pf[p]), iy = cell_y(pf[HWN + p]);  // in range by compaction
            sslot[local] = g_slot[b*NCELL + iy*NXG + ix];
        }
    }
    __syncthreads();
    if (!active) return;

    float w0 = sw[local][0], w1 = sw[local][1], w2 = sw[local][2];
    int   j0 = si[local][0], j1 = si[local][1], j2 = si[local][2];
    const float* fT = g_fvT + (size_t)b*HWN*CC;
    // einsum order: (w0*g0 + w1*g1) + w2*g2, no fma
    float f = __fadd_rn(__fadd_rn(__fmul_rn(w0, fT[(size_t)j0*CC + lane64]),
                                  __fmul_rn(w1, fT[(size_t)j1*CC + lane64])),
                        __fmul_rn(w2, fT[(size_t)j2*CC + lane64]));
    atomicAdd(g_acc + ((size_t)(b*MAXSLOT + sslot[local]))*CC + lane64, f);
}

// ---------------------------------------------------------------------------
// 4. paint: single streaming pass over the 134 MB output.
//    out[b][ch][cell] = cnt>0 ? acc[slot][ch]/cnt : 0.  Coalesced writes;
//    gathers hit only the ~6% touched cells (L2-resident 8 MB acc).
// ---------------------------------------------------------------------------
__global__ void __launch_bounds__(256) paint_kernel(float* __restrict__ out) {
    int b = blockIdx.y;
    int cell = blockIdx.x * 256 + threadIdx.x;   // grid.x = NCELL/256
    float c = g_cnt[b*NCELL + cell];
    float* ob = out + (size_t)b*CC*NCELL + cell;
    if (c > 0.0f) {
        const float* a = g_acc + ((size_t)(b*MAXSLOT + g_slot[b*NCELL + cell]))*CC;
        #pragma unroll 8
        for (int ch = 0; ch < CC; ch++)
            ob[(size_t)ch*NCELL] = __fdiv_rn(a[ch], c);
    } else {
        #pragma unroll 8
        for (int ch = 0; ch < CC; ch++)
            ob[(size_t)ch*NCELL] = 0.0f;
    }
}

extern "C" void kernel_launch(void* const* d_in, const int* in_sizes, int n_in,
                              void* d_out, int out_size) {
    const float* fv    = (const float*)d_in[0];   // (B,C,H,W)
    const float* pif   = (const float*)d_in[1];   // (B,4,H,W)
    const int*   mask  = (const int*)  d_in[2];   // (B,H,W)
    const float* piff  = (const float*)d_in[3];   // (B,4,H,W)
    const int*   maskf = (const int*)  d_in[4];   // (B,H,W)
    float* out = (float*)d_out;                   // (B,C,NY,NX)

    init_kernel<<<INIT_BLKS, 256>>>();

    prep_kernel<<<PREP_BLKS, 256>>>(fv, pif, mask, piff, maskf);

    knn_kernel<<<dim3(HWN/256, SCH, BB), 256>>>(piff);

    scatter_kernel<<<dim3(HWN/4, BB, 2), 256>>>(piff);

    paint_kernel<<<dim3(NCELL/256, BB), 256>>>(out);
}

// round 14
// speedup vs baseline: 1.3292x; 1.3292x over previous
#include <cuda_runtime.h>

// Problem constants
#define BB 2
#define CC 64
#define HH 64
#define WW 128
#define HWN (HH*WW)         // 8192
#define NXG 512
#define NYG 512
#define NCELL (NXG*NYG)     // 262144
#define POS_INF (3.402823466e38f)
#define IDX_INF 0x7fffffff

// prep_kernel block-range dispatch: compact first (long pole), then transpose,
// then the big d_out zero.
#define CP_BLKS   BB
#define TR_BLKS   1024      // (HWN/32) * (CC/32) * BB
#define ZOUT_BLKS 4096      // (BB*CC*NCELL/4) / (256*8)
#define PREP_BLKS (CP_BLKS + TR_BLKS + ZOUT_BLKS)

// Scratch (device globals — no runtime allocation allowed)
__device__ float  g_fvT[BB*HWN*CC];          // transposed features (B, HW, C)
__device__ float4 g_nearc[BB*HWN];           // compacted near pts {x,y,z,|n|^2} + sentinels
__device__ int    g_near_idx[BB*HWN];        // original index of compacted near pts
__device__ int    g_near_cnt[BB];
__device__ int    g_far_idx[BB*HWN];         // compacted valid+in-range far point indices
__device__ int    g_far_cnt[BB];
__device__ float  g_cnt[BB*NCELL];           // per-cell point counts (zeroed per call)

// Sorted-insert of smallest-3, strict '<' so earlier indices win ties
#define INS(val, jj) do {                                             \
    if ((val) < s2) {                                                 \
        if ((val) < s1) {                                             \
            s2 = s1; i2 = i1;                                         \
            if ((val) < s0) { s1 = s0; i1 = i0; s0 = (val); i0 = (jj); } \
            else            { s1 = (val); i1 = (jj); }                \
        } else { s2 = (val); i2 = (jj); }                             \
    }                                                                 \
} while (0)

__device__ __forceinline__ int cell_x(float x) { return (int)floorf(__fdiv_rn(x, 0.1f)); }
__device__ __forceinline__ int cell_y(float y) { return (int)floorf(__fdiv_rn(__fsub_rn(y, -25.6f), 0.1f)); }

// |p|^2 with the reference's rounding: ((x*x + y*y) + z*z), no fma contraction
__device__ __forceinline__ float sqnorm_ref(float x, float y, float z) {
    return __fadd_rn(__fadd_rn(__fmul_rn(x, x), __fmul_rn(y, y)), __fmul_rn(z, z));
}

// GEMM-replica pair distance: acc = rn(a0*b0); acc = fma(a1,b1,acc); acc = fma(a2,b2,acc);
// d2 = rn( rn(fsq+nsq) - acc ).  Pre-doubled f is bit-equal to the alpha=2 folded GEMM.
__device__ __forceinline__ float d2_ref(float fx2, float fy2, float fz2, float fsq,
                                        float nx, float ny, float nz, float nsq) {
    float acc = __fmul_rn(fx2, nx);
    acc = __fmaf_rn(fy2, ny, acc);
    acc = __fmaf_rn(fz2, nz, acc);
    return __fsub_rn(__fadd_rn(fsq, nsq), acc);
}

// ---------------------------------------------------------------------------
// 0. zero g_cnt — separate launch (prep's counting atomics must not race it)
// ---------------------------------------------------------------------------
__global__ void __launch_bounds__(256) init_kernel() {
    float4* c4 = (float4*)g_cnt;
    size_t i = (size_t)blockIdx.x * 256 + threadIdx.x;   // 512 blocks
    c4[i] = make_float4(0.f, 0.f, 0.f, 0.f);
}

// ---------------------------------------------------------------------------
// 1. prep: compact(+count) at bid 0..1, transpose, then zero d_out
// ---------------------------------------------------------------------------
__global__ void __launch_bounds__(256) prep_kernel(const float* __restrict__ fv,
                                                   const float* __restrict__ pif,
                                                   const int*   __restrict__ mask,
                                                   const float* __restrict__ piff,
                                                   const int*   __restrict__ maskf,
                                                   float* __restrict__ out) {
    int bid = blockIdx.x;
    int tid = threadIdx.x;

    if (bid >= CP_BLKS) {
        bid -= CP_BLKS;
        if (bid < TR_BLKS) {                     // ---- transpose ----
            __shared__ float tile[32][33];
            int b  = bid / ((HWN/32) * (CC/32));
            int r  = bid % ((HWN/32) * (CC/32));
            int c0 = (r / (HWN/32)) * 32;
            int p0 = (r % (HWN/32)) * 32;
            int tx = tid & 31, ty = tid >> 5;    // 32 x 8
            #pragma unroll
            for (int i = ty; i < 32; i += 8)
                tile[i][tx] = fv[((size_t)b*CC + c0 + i) * HWN + p0 + tx];
            __syncthreads();
            #pragma unroll
            for (int i = ty; i < 32; i += 8)
                g_fvT[((size_t)b*HWN + p0 + i) * CC + c0 + tx] = tile[tx][i];
            return;
        }
        bid -= TR_BLKS;                          // ---- zero d_out ----
        float4* o4 = (float4*)out;
        size_t base = (size_t)bid * 2048 + tid;
        const float4 z = make_float4(0.f, 0.f, 0.f, 0.f);
        #pragma unroll
        for (int i = 0; i < 8; i++)
            o4[base + (size_t)i * 256] = z;
        return;
    }

    // ---- compaction + counting (1 block per batch), ballot + block scan ----
    int b = bid;
    int warp = tid >> 5, lane = tid & 31;
    __shared__ unsigned smask[256];              // validity masks, index-ordered chunks
    __shared__ int sscan[256];                   // inclusive scan of popcounts

    // ===== phase A: near (compaction predicate = mask > 0) =====
    const int*   mn = mask + b * HWN;
    const float* pn = pif + (size_t)b * 4 * HWN;
    #pragma unroll 4
    for (int r = 0; r < 32; r++) {
        int p = r * 256 + tid;                   // coalesced
        unsigned m = __ballot_sync(0xffffffffu, mn[p] > 0);
        if (lane == 0) smask[r*8 + warp] = m;    // chunk key = p/32
    }
    __syncthreads();
    sscan[tid] = __popc(smask[tid]);
    __syncthreads();
    #pragma unroll
    for (int off = 1; off < 256; off <<= 1) {
        int v = (tid >= off) ? sscan[tid - off] : 0;
        __syncthreads();
        sscan[tid] += v;
        __syncthreads();
    }
    int ncnt_total = sscan[255];
    if (tid == 255) g_near_cnt[b] = ncnt_total;
    #pragma unroll 4
    for (int r = 0; r < 32; r++) {
        int p = r * 256 + tid;
        if (mn[p] > 0) {
            int key = r*8 + warp;
            unsigned m = smask[key];
            int rank = sscan[key] - __popc(m) + __popc(m & ((1u << lane) - 1u));
            float x = pn[p], y = pn[HWN + p], z = pn[2*HWN + p];
            g_nearc[b*HWN + rank] = make_float4(x, y, z, sqnorm_ref(x, y, z));
            g_near_idx[b*HWN + rank] = p;
            // count: valid near point that lands in the BEV grid
            int ix = cell_x(x), iy = cell_y(y);
            if (ix >= 0 && ix < NXG && iy >= 0 && iy < NYG)
                atomicAdd(&g_cnt[b*NCELL + iy*NXG + ix], 1.0f);
        }
    }
    // pad g_nearc to a multiple of 128 with never-selected sentinels
    {
        int pad = (ncnt_total + 127) & ~127;
        if (pad > HWN) pad = HWN;
        for (int i = ncnt_total + tid; i < pad; i += 256)
            g_nearc[b*HWN + i] = make_float4(0.f, 0.f, 0.f, 1e30f);
    }
    __syncthreads();

    // ===== phase B: far (predicate = mask > 0 && cell in range) =====
    const int*   mf  = maskf + b * HWN;
    const float* pff = piff + (size_t)b * 4 * HWN;
    #pragma unroll 4
    for (int r = 0; r < 32; r++) {
        int p = r * 256 + tid;
        bool v = mf[p] > 0;
        if (v) {
            int ix = cell_x(pff[p]), iy = cell_y(pff[HWN + p]);
            v = (ix >= 0 && ix < NXG && iy >= 0 && iy < NYG);
        }
        unsigned m = __ballot_sync(0xffffffffu, v);
        if (lane == 0) smask[r*8 + warp] = m;
    }
    __syncthreads();
    sscan[tid] = __popc(smask[tid]);
    __syncthreads();
    #pragma unroll
    for (int off = 1; off < 256; off <<= 1) {
        int v = (tid >= off) ? sscan[tid - off] : 0;
        __syncthreads();
        sscan[tid] += v;
        __syncthreads();
    }
    if (tid == 255) g_far_cnt[b] = sscan[255];
    #pragma unroll 4
    for (int r = 0; r < 32; r++) {
        int p = r * 256 + tid;
        int key = r*8 + warp;
        unsigned m = smask[key];
        if ((m >> lane) & 1u) {
            int rank = sscan[key] - __popc(m) + __popc(m & ((1u << lane) - 1u));
            g_far_idx[b*HWN + rank] = p;
            int ix = cell_x(pff[p]), iy = cell_y(pff[HWN + p]);
            atomicAdd(&g_cnt[b*NCELL + iy*NXG + ix], 1.0f);
        }
    }
}

// ---------------------------------------------------------------------------
// 2. fused kNN + scatter (pre-divided atomics into out).
//    blockIdx.z = 0: near points (64 lanes/pt, 4 pts/block).
//    blockIdx.z = 1: far points — phase 1: warp w (of 4) scans ALL compacted
//    near points for point w (lane-strided, L1-resident LDG), per-lane top-3,
//    then 3-round (value,idx) shuffle argmin merge == stable top-3.
//    Phase 2: 64-lane channel gather + atomicAdd(out, f/cnt).
// ---------------------------------------------------------------------------
__global__ void __launch_bounds__(256) scatter_kernel(const float* __restrict__ pif_far,
                                                      float* __restrict__ out) {
    int b = blockIdx.y;
    int local = threadIdx.x >> 6;                // point-in-block 0..3
    int lane64 = threadIdx.x & 63;

    if (blockIdx.z == 0) {
        int slot = blockIdx.x * 4 + local;
        if (slot >= g_near_cnt[b]) return;
        float4 q = g_nearc[b*HWN + slot];
        int ix = cell_x(q.x), iy = cell_y(q.y);
        if (ix < 0 || ix >= NXG || iy < 0 || iy >= NYG) return;
        int cell = iy * NXG + ix;
        int p = g_near_idx[b*HWN + slot];
        float c = g_cnt[b*NCELL + cell];         // >= 1 here
        float f = g_fvT[((size_t)b*HWN + p) * CC + lane64];   // coalesced
        atomicAdd(out + (size_t)b*CC*NCELL + (size_t)lane64*NCELL + cell,
                  __fdiv_rn(f, c));
        return;
    }

    // ---- far path ----
    __shared__ float sw[4][3];
    __shared__ int   si[4][3];
    __shared__ int   scell[4];

    int fcnt = g_far_cnt[b];
    int warp = threadIdx.x >> 5;                 // 0..7
    int lane = threadIdx.x & 31;

    // phase 1: warps 0..3 each own one far point
    if (warp < 4) {
        int slot = blockIdx.x * 4 + warp;
        if (slot < fcnt) {
            int p = g_far_idx[b*HWN + slot];
            const float* pf = pif_far + (size_t)b * 4 * HWN;
            float x = pf[p], y = pf[HWN + p], z = pf[2*HWN + p];
            float fsq = sqnorm_ref(x, y, z);
            float fx2 = 2.0f * x, fy2 = 2.0f * y, fz2 = 2.0f * z;  // exact

            int ncnt = g_near_cnt[b];
            int npad = (ncnt + 127) & ~127;
            if (npad > HWN) npad = HWN;          // matches prep's padding

            float s0 = POS_INF, s1 = POS_INF, s2 = POS_INF;
            int   i0 = IDX_INF, i1 = IDX_INF, i2 = IDX_INF;
            const float4* nc = g_nearc + b*HWN;

            // lane-strided scan, unrolled x4 for MLP; per-lane indices ascending
            #pragma unroll 1
            for (int j = lane; j < npad; j += 128) {
                float4 q0 = nc[j];
                float4 q1 = nc[j + 32];
                float4 q2 = nc[j + 64];
                float4 q3 = nc[j + 96];
                float d0  = d2_ref(fx2, fy2, fz2, fsq, q0.x, q0.y, q0.z, q0.w);
                float d1  = d2_ref(fx2, fy2, fz2, fsq, q1.x, q1.y, q1.z, q1.w);
                float d2v = d2_ref(fx2, fy2, fz2, fsq, q2.x, q2.y, q2.z, q2.w);
                float d3  = d2_ref(fx2, fy2, fz2, fsq, q3.x, q3.y, q3.z, q3.w);
                float m = fminf(fminf(d0, d1), fminf(d2v, d3));
                if (m < s2) {
                    INS(d0, j);
                    INS(d1, j + 32);
                    INS(d2v, j + 64);
                    INS(d3, j + 96);
                }
            }

            // 3-round warp argmin by (value, compacted index) — exactly the
            // 3 lexicographically-smallest pairs == stable top-3 of the ref.
            float a0 = s0, a1 = s1, a2 = s2;
            int   c0 = i0, c1 = i1, c2 = i2;
            float S[3]; int I[3];
            #pragma unroll
            for (int k = 0; k < 3; k++) {
                float bv = a0; int bx = c0;
                #pragma unroll
                for (int off = 16; off; off >>= 1) {
                    float ov = __shfl_down_sync(0xffffffffu, bv, off);
                    int   ox = __shfl_down_sync(0xffffffffu, bx, off);
                    if (ov < bv || (ov == bv && ox < bx)) { bv = ov; bx = ox; }
                }
                bv = __shfl_sync(0xffffffffu, bv, 0);
                bx = __shfl_sync(0xffffffffu, bx, 0);
                S[k] = bv; I[k] = bx;
                if (c0 == bx) {                  // unique index -> unique winner
                    a0 = a1; c0 = c1; a1 = a2; c1 = c2;
                    a2 = POS_INF; c2 = IDX_INF;
                }
            }
            if (lane == 0) {
                // IDW weights exactly as reference: r=1/(d+1e-8); w=r/((r0+r1)+r2)
                float r0 = __fdiv_rn(1.0f, __fadd_rn(S[0], 1e-8f));
                float r1 = __fdiv_rn(1.0f, __fadd_rn(S[1], 1e-8f));
                float r2 = __fdiv_rn(1.0f, __fadd_rn(S[2], 1e-8f));
                float rs = __fadd_rn(__fadd_rn(r0, r1), r2);
                sw[warp][0] = __fdiv_rn(r0, rs);
                sw[warp][1] = __fdiv_rn(r1, rs);
                sw[warp][2] = __fdiv_rn(r2, rs);
                si[warp][0] = g_near_idx[b*HWN + I[0]];
                si[warp][1] = g_near_idx[b*HWN + I[1]];
                si[warp][2] = g_near_idx[b*HWN + I[2]];
                int ix = cell_x(x), iy = cell_y(y);  // in range by compaction
                scell[warp] = iy * NXG + ix;
            }
        }
    }
    __syncthreads();

    // phase 2: 64-lane groups do the channel gather + scatter
    int slot = blockIdx.x * 4 + local;
    if (slot >= fcnt) return;

    float w0 = sw[local][0], w1 = sw[local][1], w2 = sw[local][2];
    int   j0 = si[local][0], j1 = si[local][1], j2 = si[local][2];
    int cell = scell[local];
    float c = g_cnt[b*NCELL + cell];             // >= 1 here
    const float* fT = g_fvT + (size_t)b*HWN*CC;
    // einsum order: (w0*g0 + w1*g1) + w2*g2, no fma
    float f = __fadd_rn(__fadd_rn(__fmul_rn(w0, fT[(size_t)j0*CC + lane64]),
                                  __fmul_rn(w1, fT[(size_t)j1*CC + lane64])),
                        __fmul_rn(w2, fT[(size_t)j2*CC + lane64]));
    atomicAdd(out + (size_t)b*CC*NCELL + (size_t)lane64*NCELL + cell,
              __fdiv_rn(f, c));
}

extern "C" void kernel_launch(void* const* d_in, const int* in_sizes, int n_in,
                              void* d_out, int out_size) {
    const float* fv    = (const float*)d_in[0];   // (B,C,H,W)
    const float* pif   = (const float*)d_in[1];   // (B,4,H,W)
    const int*   mask  = (const int*)  d_in[2];   // (B,H,W)
    const float* piff  = (const float*)d_in[3];   // (B,4,H,W)
    const int*   maskf = (const int*)  d_in[4];   // (B,H,W)
    float* out = (float*)d_out;                   // (B,C,NY,NX)

    init_kernel<<<BB*NCELL/4/256, 256>>>();

    prep_kernel<<<PREP_BLKS, 256>>>(fv, pif, mask, piff, maskf, out);

    scatter_kernel<<<dim3(HWN/4, BB, 2), 256>>>(piff, out);
}

// round 15
// speedup vs baseline: 1.4845x; 1.1168x over previous
#include <cuda_runtime.h>

// Problem constants
#define BB 2
#define CC 64
#define HH 64
#define WW 128
#define HWN (HH*WW)         // 8192
#define NXG 512
#define NYG 512
#define NCELL (NXG*NYG)     // 262144
#define SCH 32              // near-chunk slots (dynamic count may use fewer)
#define NCHUNK 256
#define POS_INF (3.402823466e38f)
#define IDX_INF 0x7fffffff

// prep_kernel block-range dispatch: compact first (straggler), then transpose,
// then zero d_out, then zero g_cnt. No block touches g_cnt atomically here.
#define CP_BLKS   BB
#define TR_BLKS   1024      // (HWN/32) * (CC/32) * BB
#define ZOUT_BLKS 4096      // (BB*CC*NCELL/4) / (256*8)
#define ZCNT_BLKS 64        // (BB*NCELL/4) / (256*8)
#define PREP_BLKS (CP_BLKS + TR_BLKS + ZOUT_BLKS + ZCNT_BLKS)

// Scratch (device globals — no runtime allocation allowed)
__device__ float  g_fvT[BB*HWN*CC];          // transposed features (B, HW, C)
__device__ float4 g_nearc[BB*HWN];           // compacted valid near pts {x,y,z,|n|^2}
__device__ int    g_near_idx[BB*HWN];        // original index of compacted near pts
__device__ int    g_near_cnt[BB];
__device__ int    g_far_idx[BB*HWN];         // compacted valid+in-range far point indices
__device__ int    g_far_cnt[BB];
__device__ float4 g_ps[BB*SCH*HWN];          // partial top-3 d2 {s0,s1,s2,-} [b][chunk][slot]
__device__ int4   g_pi[BB*SCH*HWN];          // partial top-3 compacted idx {i0,i1,i2,-}
__device__ float  g_cnt[BB*NCELL];           // per-cell point counts (zeroed in prep)

// Sorted-insert of smallest-3, strict '<' so earlier indices win ties
#define INS(val, jj) do {                                             \
    if ((val) < s2) {                                                 \
        if ((val) < s1) {                                             \
            s2 = s1; i2 = i1;                                         \
            if ((val) < s0) { s1 = s0; i1 = i0; s0 = (val); i0 = (jj); } \
            else            { s1 = (val); i1 = (jj); }                \
        } else { s2 = (val); i2 = (jj); }                             \
    }                                                                 \
} while (0)

__device__ __forceinline__ int cell_x(float x) { return (int)floorf(__fdiv_rn(x, 0.1f)); }
__device__ __forceinline__ int cell_y(float y) { return (int)floorf(__fdiv_rn(__fsub_rn(y, -25.6f), 0.1f)); }

// |p|^2 with the reference's rounding: ((x*x + y*y) + z*z), no fma contraction
__device__ __forceinline__ float sqnorm_ref(float x, float y, float z) {
    return __fadd_rn(__fadd_rn(__fmul_rn(x, x), __fmul_rn(y, y)), __fmul_rn(z, z));
}

// GEMM-replica pair distance: acc = rn(a0*b0); acc = fma(a1,b1,acc); acc = fma(a2,b2,acc);
// d2 = rn( rn(fsq+nsq) - acc ).  Pre-doubled f is bit-equal to the alpha=2 folded GEMM.
__device__ __forceinline__ float d2_ref(float fx2, float fy2, float fz2, float fsq,
                                        float nx, float ny, float nz, float nsq) {
    float acc = __fmul_rn(fx2, nx);
    acc = __fmaf_rn(fy2, ny, acc);
    acc = __fmaf_rn(fz2, nz, acc);
    return __fsub_rn(__fadd_rn(fsq, nsq), acc);
}

// ---------------------------------------------------------------------------
// 1. prep: compact (bid 0..1) ∥ transpose ∥ zero d_out ∥ zero g_cnt.
//    Compact does NOT touch g_cnt (counting moved to K2) -> no race.
// ---------------------------------------------------------------------------
__global__ void __launch_bounds__(256) prep_kernel(const float* __restrict__ fv,
                                                   const float* __restrict__ pif,
                                                   const int*   __restrict__ mask,
                                                   const float* __restrict__ piff,
                                                   const int*   __restrict__ maskf,
                                                   float* __restrict__ out) {
    int bid = blockIdx.x;
    int tid = threadIdx.x;

    if (bid >= CP_BLKS) {
        bid -= CP_BLKS;
        if (bid < TR_BLKS) {                     // ---- transpose ----
            __shared__ float tile[32][33];
            int b  = bid / ((HWN/32) * (CC/32));
            int r  = bid % ((HWN/32) * (CC/32));
            int c0 = (r / (HWN/32)) * 32;
            int p0 = (r % (HWN/32)) * 32;
            int tx = tid & 31, ty = tid >> 5;    // 32 x 8
            #pragma unroll
            for (int i = ty; i < 32; i += 8)
                tile[i][tx] = fv[((size_t)b*CC + c0 + i) * HWN + p0 + tx];
            __syncthreads();
            #pragma unroll
            for (int i = ty; i < 32; i += 8)
                g_fvT[((size_t)b*HWN + p0 + i) * CC + c0 + tx] = tile[tx][i];
            return;
        }
        bid -= TR_BLKS;
        const float4 z = make_float4(0.f, 0.f, 0.f, 0.f);
        if (bid < ZOUT_BLKS) {                   // ---- zero d_out ----
            float4* o4 = (float4*)out;
            size_t base = (size_t)bid * 2048 + tid;
            #pragma unroll
            for (int i = 0; i < 8; i++)
                o4[base + (size_t)i * 256] = z;
            return;
        }
        bid -= ZOUT_BLKS;                        // ---- zero g_cnt ----
        float4* c4 = (float4*)g_cnt;
        size_t base = (size_t)bid * 2048 + tid;
        #pragma unroll
        for (int i = 0; i < 8; i++)
            c4[base + (size_t)i * 256] = z;
        return;
    }

    // ---- ordered compaction (1 block per batch), ballot + block scan ----
    int b = bid;
    int warp = tid >> 5, lane = tid & 31;
    __shared__ unsigned smask[256];              // validity masks, index-ordered chunks
    __shared__ int sscan[256];                   // inclusive scan of popcounts

    // ===== phase A: near (compaction predicate = mask > 0) =====
    const int*   mn = mask + b * HWN;
    const float* pn = pif + (size_t)b * 4 * HWN;
    #pragma unroll 4
    for (int r = 0; r < 32; r++) {
        int p = r * 256 + tid;                   // coalesced
        unsigned m = __ballot_sync(0xffffffffu, mn[p] > 0);
        if (lane == 0) smask[r*8 + warp] = m;    // chunk key = p/32
    }
    __syncthreads();
    sscan[tid] = __popc(smask[tid]);
    __syncthreads();
    #pragma unroll
    for (int off = 1; off < 256; off <<= 1) {
        int v = (tid >= off) ? sscan[tid - off] : 0;
        __syncthreads();
        sscan[tid] += v;
        __syncthreads();
    }
    if (tid == 255) g_near_cnt[b] = sscan[255];
    #pragma unroll 4
    for (int r = 0; r < 32; r++) {
        int p = r * 256 + tid;
        if (mn[p] > 0) {
            int key = r*8 + warp;
            unsigned m = smask[key];
            int rank = sscan[key] - __popc(m) + __popc(m & ((1u << lane) - 1u));
            float x = pn[p], y = pn[HWN + p], z = pn[2*HWN + p];
            g_nearc[b*HWN + rank] = make_float4(x, y, z, sqnorm_ref(x, y, z));
            g_near_idx[b*HWN + rank] = p;
        }
    }
    __syncthreads();

    // ===== phase B: far (predicate = mask > 0 && cell in range) =====
    const int*   mf  = maskf + b * HWN;
    const float* pff = piff + (size_t)b * 4 * HWN;
    #pragma unroll 4
    for (int r = 0; r < 32; r++) {
        int p = r * 256 + tid;
        bool v = mf[p] > 0;
        if (v) {
            int ix = cell_x(pff[p]), iy = cell_y(pff[HWN + p]);
            v = (ix >= 0 && ix < NXG && iy >= 0 && iy < NYG);
        }
        unsigned m = __ballot_sync(0xffffffffu, v);
        if (lane == 0) smask[r*8 + warp] = m;
    }
    __syncthreads();
    sscan[tid] = __popc(smask[tid]);
    __syncthreads();
    #pragma unroll
    for (int off = 1; off < 256; off <<= 1) {
        int v = (tid >= off) ? sscan[tid - off] : 0;
        __syncthreads();
        sscan[tid] += v;
        __syncthreads();
    }
    if (tid == 255) g_far_cnt[b] = sscan[255];
    #pragma unroll 4
    for (int r = 0; r < 32; r++) {
        int p = r * 256 + tid;
        int key = r*8 + warp;
        unsigned m = smask[key];
        if ((m >> lane) & 1u) {
            int rank = sscan[key] - __popc(m) + __popc(m & ((1u << lane) - 1u));
            g_far_idx[b*HWN + rank] = p;
        }
    }
}

// ---------------------------------------------------------------------------
// 2. kNN + cell counting in ONE launch.
//    blockIdx.x < 32 : kNN blocks (thread = far point, smem chunk of near pts)
//    blockIdx.x == 32: counting blocks — 256 compacted points per block,
//    atomicAdd into g_cnt (zeroed in prep). Runs concurrent with kNN.
// ---------------------------------------------------------------------------
__global__ void __launch_bounds__(256) knn_kernel(const float* __restrict__ pif_far) {
    int b  = blockIdx.z;
    int tid = threadIdx.x;

    if (blockIdx.x == 32) {                      // ---- counting slice ----
        int slot = blockIdx.y * 256 + tid;
        if (slot < g_near_cnt[b]) {
            float4 q = g_nearc[b*HWN + slot];
            int ix = cell_x(q.x), iy = cell_y(q.y);
            if (ix >= 0 && ix < NXG && iy >= 0 && iy < NYG)
                atomicAdd(&g_cnt[b*NCELL + iy*NXG + ix], 1.0f);
        }
        if (slot < g_far_cnt[b]) {
            int p = g_far_idx[b*HWN + slot];
            const float* pf = pif_far + (size_t)b * 4 * HWN;
            int ix = cell_x(pf[p]), iy = cell_y(pf[HWN + p]);  // in range by compaction
            atomicAdd(&g_cnt[b*NCELL + iy*NXG + ix], 1.0f);
        }
        return;
    }

    // ---- kNN ----
    __shared__ float4 sh[NCHUNK];
    int ch = blockIdx.y;
    int nbase = ch * NCHUNK;
    int ncnt = g_near_cnt[b];
    if (nbase >= ncnt) return;
    if (blockIdx.x * 256 >= g_far_cnt[b]) return;

    int navail = min(NCHUNK, ncnt - nbase);
    int n8 = (navail + 7) & ~7;                  // pad to multiple of 8
    const float4* src = g_nearc + b*HWN + nbase;
    for (int i = tid; i < n8; i += 256)
        sh[i] = (i < navail) ? src[i] : make_float4(0.f, 0.f, 0.f, 1e30f);
    __syncthreads();

    int slot = blockIdx.x * 256 + tid;
    if (slot >= g_far_cnt[b]) return;
    int p = g_far_idx[b*HWN + slot];

    const float* pf = pif_far + (size_t)b * 4 * HWN;
    float x = pf[p], y = pf[HWN + p], z = pf[2*HWN + p];
    float fsq = sqnorm_ref(x, y, z);
    float fx2 = 2.0f * x, fy2 = 2.0f * y, fz2 = 2.0f * z;  // exact

    float s0 = POS_INF, s1 = POS_INF, s2 = POS_INF;
    int   i0 = 0, i1 = 0, i2 = 0;

    #pragma unroll 1
    for (int j = 0; j < n8; j += 8) {
        float d[8];
        #pragma unroll
        for (int u = 0; u < 8; u++) {
            float4 q = sh[j + u];
            d[u] = d2_ref(fx2, fy2, fz2, fsq, q.x, q.y, q.z, q.w);
        }
        float m = fminf(fminf(fminf(d[0], d[1]), fminf(d[2], d[3])),
                        fminf(fminf(d[4], d[5]), fminf(d[6], d[7])));
        if (m < s2) {   // rarely taken
            #pragma unroll
            for (int u = 0; u < 8; u++) INS(d[u], nbase + j + u);
        }
    }

    int base = (b*SCH + ch) * HWN + slot;
    g_ps[base] = make_float4(s0, s1, s2, 0.0f);
    g_pi[base] = make_int4(i0, i1, i2, 0);
}

// ---------------------------------------------------------------------------
// 3. fused scatter with pre-divided terms: atomicAdd(out, f / cnt[cell]).
//    blockIdx.z = 0: near points (64 lanes/pt).
//    blockIdx.z = 1: far points — warp-parallel top-3 merge, IDW weights
//    (reference rounding), then 64-lane gather+scatter.
// ---------------------------------------------------------------------------
__global__ void __launch_bounds__(256) scatter_kernel(const float* __restrict__ pif_far,
                                                      float* __restrict__ out) {
    int b = blockIdx.y;
    int local = threadIdx.x >> 6;                // point-in-block 0..3
    int lane64 = threadIdx.x & 63;
    int slot = blockIdx.x * 4 + local;

    if (blockIdx.z == 0) {
        if (slot >= g_near_cnt[b]) return;
        float4 q = g_nearc[b*HWN + slot];
        int ix = cell_x(q.x), iy = cell_y(q.y);
        if (ix < 0 || ix >= NXG || iy < 0 || iy >= NYG) return;
        int cell = iy * NXG + ix;
        int p = g_near_idx[b*HWN + slot];
        float c = g_cnt[b*NCELL + cell];         // >= 1 here
        float f = g_fvT[((size_t)b*HWN + p) * CC + lane64];   // coalesced
        atomicAdd(out + (size_t)b*CC*NCELL + (size_t)lane64*NCELL + cell,
                  __fdiv_rn(f, c));
        return;
    }

    // ---- far path ----
    __shared__ float sw[4][3];
    __shared__ int   si[4][3];
    __shared__ int   scell[4];

    int fcnt = g_far_cnt[b];
    bool active = slot < fcnt;
    int half = lane64 >> 5;                      // warp-half within the point
    int lane = lane64 & 31;                      // chunk id for half 0

    if (active && half == 0) {
        // lane = chunk; load this chunk's sorted top-3 partial (or sentinels)
        int ncnt = g_near_cnt[b];
        float a0 = POS_INF, a1 = POS_INF, a2 = POS_INF;
        int   c0 = IDX_INF,  c1 = IDX_INF,  c2 = IDX_INF;
        if (lane * NCHUNK < ncnt) {
            int base = (b*SCH + lane) * HWN + slot;
            float4 v = g_ps[base];
            int4  iv = g_pi[base];
            a0 = v.x; a1 = v.y; a2 = v.z;
            c0 = iv.x; c1 = iv.y; c2 = iv.z;
        }
        // 3-round warp argmin by (value, then compacted index) — identical to
        // sequential INS order (chunks partition ascending indices; within-chunk
        // triples are index-ordered on equal values).
        float S[3]; int I[3];
        #pragma unroll
        for (int k = 0; k < 3; k++) {
            float bv = a0; int bx = c0;
            #pragma unroll
            for (int off = 16; off; off >>= 1) {
                float ov = __shfl_down_sync(0xffffffffu, bv, off);
                int   ox = __shfl_down_sync(0xffffffffu, bx, off);
                if (ov < bv || (ov == bv && ox < bx)) { bv = ov; bx = ox; }
            }
            bv = __shfl_sync(0xffffffffu, bv, 0);
            bx = __shfl_sync(0xffffffffu, bx, 0);
            S[k] = bv; I[k] = bx;
            if (c0 == bx) {                      // unique index -> unique winner
                a0 = a1; c0 = c1; a1 = a2; c1 = c2;
                a2 = POS_INF; c2 = IDX_INF;
            }
        }
        if (lane == 0) {
            // IDW weights exactly as reference: r = 1/(d+1e-8); w = r/((r0+r1)+r2)
            float r0 = __fdiv_rn(1.0f, __fadd_rn(S[0], 1e-8f));
            float r1 = __fdiv_rn(1.0f, __fadd_rn(S[1], 1e-8f));
            float r2 = __fdiv_rn(1.0f, __fadd_rn(S[2], 1e-8f));
            float rs = __fadd_rn(__fadd_rn(r0, r1), r2);
            sw[local][0] = __fdiv_rn(r0, rs);
            sw[local][1] = __fdiv_rn(r1, rs);
            sw[local][2] = __fdiv_rn(r2, rs);
            si[local][0] = g_near_idx[b*HWN + I[0]];
            si[local][1] = g_near_idx[b*HWN + I[1]];
            si[local][2] = g_near_idx[b*HWN + I[2]];
            int p = g_far_idx[b*HWN + slot];
            const float* pf = pif_far + (size_t)b * 4 * HWN;
            int ix = cell_x(pf[p]), iy = cell_y(pf[HWN + p]);  // in range by compaction
            scell[local] = iy * NXG + ix;
        }
    }
    __syncthreads();
    if (!active) return;

    float w0 = sw[local][0], w1 = sw[local][1], w2 = sw[local][2];
    int   j0 = si[local][0], j1 = si[local][1], j2 = si[local][2];
    int cell = scell[local];
    float c = g_cnt[b*NCELL + cell];             // >= 1 here
    const float* fT = g_fvT + (size_t)b*HWN*CC;
    // einsum order: (w0*g0 + w1*g1) + w2*g2, no fma
    float f = __fadd_rn(__fadd_rn(__fmul_rn(w0, fT[(size_t)j0*CC + lane64]),
                                  __fmul_rn(w1, fT[(size_t)j1*CC + lane64])),
                        __fmul_rn(w2, fT[(size_t)j2*CC + lane64]));
    atomicAdd(out + (size_t)b*CC*NCELL + (size_t)lane64*NCELL + cell,
              __fdiv_rn(f, c));
}

extern "C" void kernel_launch(void* const* d_in, const int* in_sizes, int n_in,
                              void* d_out, int out_size) {
    const float* fv    = (const float*)d_in[0];   // (B,C,H,W)
    const float* pif   = (const float*)d_in[1];   // (B,4,H,W)
    const int*   mask  = (const int*)  d_in[2];   // (B,H,W)
    const float* piff  = (const float*)d_in[3];   // (B,4,H,W)
    const int*   maskf = (const int*)  d_in[4];   // (B,H,W)
    float* out = (float*)d_out;                   // (B,C,NY,NX)

    prep_kernel<<<PREP_BLKS, 256>>>(fv, pif, mask, piff, maskf, out);

    // x: 0..31 kNN far-blocks, 32 = counting slice; y: chunks; z: batch
    knn_kernel<<<dim3(33, SCH, BB), 256>>>(piff);

    scatter_kernel<<<dim3(HWN/4, BB, 2), 256>>>(piff, out);
}

// round 17
// speedup vs baseline: 1.6731x; 1.1271x over previous
#include <cuda_runtime.h>

// Problem constants
#define BB 2
#define CC 64
#define HH 64
#define WW 128
#define HWN (HH*WW)         // 8192
#define NXG 512
#define NYG 512
#define NCELL (NXG*NYG)     // 262144
#define SCH 32              // near-chunk slots (dynamic count may use fewer)
#define NCHUNK 256
#define POS_INF (3.402823466e38f)
#define IDX_INF 0x7fffffff

// K1 dispatch: compact (2) + zero g_cnt (64)
#define K1_BLKS (BB + 64)

// K2 dispatch: interleaved 1:1 — even bid: task k=bid/2, odd bid: zero chunk
//   tasks: [0,2048) knn, [2048,2112) count, [2112,3136) transpose
#define KNN_TASKS  2048     // 32 far-blocks x 32 chunks x 2 batches
#define CNT_TASKS  64
#define TR_TASKS   1024
#define K2_TASKS   (KNN_TASKS + CNT_TASKS + TR_TASKS)   // 3136
#define ZOUT_CHUNKS 4096    // each zeroes 32 KB of d_out
#define K2_BLKS (2 * ZOUT_CHUNKS)                       // 8192

// Scratch (device globals — no runtime allocation allowed)
__device__ float  g_fvT[BB*HWN*CC];          // transposed features (B, HW, C)
__device__ float4 g_nearc[BB*HWN];           // compacted valid near pts {x,y,z,|n|^2}
__device__ int    g_near_idx[BB*HWN];        // original index of compacted near pts
__device__ int    g_near_cnt[BB];
__device__ int    g_far_idx[BB*HWN];         // compacted valid+in-range far point indices
__device__ int    g_far_cnt[BB];
__device__ float4 g_ps[BB*SCH*HWN];          // partial top-3 d2 {s0,s1,s2,-} [b][chunk][slot]
__device__ int4   g_pi[BB*SCH*HWN];          // partial top-3 compacted idx {i0,i1,i2,-}
__device__ float  g_cnt[BB*NCELL];           // per-cell point counts (zeroed in K1)

// Sorted-insert of smallest-3, strict '<' so earlier indices win ties
#define INS(val, jj) do {                                             \
    if ((val) < s2) {                                                 \
        if ((val) < s1) {                                             \
            s2 = s1; i2 = i1;                                         \
            if ((val) < s0) { s1 = s0; i1 = i0; s0 = (val); i0 = (jj); } \
            else            { s1 = (val); i1 = (jj); }                \
        } else { s2 = (val); i2 = (jj); }                             \
    }                                                                 \
} while (0)

__device__ __forceinline__ int cell_x(float x) { return (int)floorf(__fdiv_rn(x, 0.1f)); }
__device__ __forceinline__ int cell_y(float y) { return (int)floorf(__fdiv_rn(__fsub_rn(y, -25.6f), 0.1f)); }

// |p|^2 with the reference's rounding: ((x*x + y*y) + z*z), no fma contraction
__device__ __forceinline__ float sqnorm_ref(float x, float y, float z) {
    return __fadd_rn(__fadd_rn(__fmul_rn(x, x), __fmul_rn(y, y)), __fmul_rn(z, z));
}

// GEMM-replica pair distance: acc = rn(a0*b0); acc = fma(a1,b1,acc); acc = fma(a2,b2,acc);
// d2 = rn( rn(fsq+nsq) - acc ).  Pre-doubled f is bit-equal to the alpha=2 folded GEMM.
__device__ __forceinline__ float d2_ref(float fx2, float fy2, float fz2, float fsq,
                                        float nx, float ny, float nz, float nsq) {
    float acc = __fmul_rn(fx2, nx);
    acc = __fmaf_rn(fy2, ny, acc);
    acc = __fmaf_rn(fz2, nz, acc);
    return __fsub_rn(__fadd_rn(fsq, nsq), acc);
}

// ---------------------------------------------------------------------------
// K1: compaction (2 blocks, no g_cnt touches) + zero g_cnt (64 blocks)
// ---------------------------------------------------------------------------
__global__ void __launch_bounds__(256) k1_kernel(const float* __restrict__ pif,
                                                 const int*   __restrict__ mask,
                                                 const float* __restrict__ piff,
                                                 const int*   __restrict__ maskf) {
    int bid = blockIdx.x;
    int tid = threadIdx.x;

    if (bid >= BB) {                             // ---- zero g_cnt ----
        float4* c4 = (float4*)g_cnt;
        size_t base = (size_t)(bid - BB) * 2048 + tid;
        const float4 z = make_float4(0.f, 0.f, 0.f, 0.f);
        #pragma unroll
        for (int i = 0; i < 8; i++)
            c4[base + (size_t)i * 256] = z;
        return;
    }

    // ---- ordered compaction (1 block per batch), ballot + block scan ----
    int b = bid;
    int warp = tid >> 5, lane = tid & 31;
    __shared__ unsigned smask[256];              // validity masks, index-ordered chunks
    __shared__ int sscan[256];                   // inclusive scan of popcounts

    // ===== phase A: near (compaction predicate = mask > 0) =====
    const int*   mn = mask + b * HWN;
    const float* pn = pif + (size_t)b * 4 * HWN;
    #pragma unroll 4
    for (int r = 0; r < 32; r++) {
        int p = r * 256 + tid;                   // coalesced
        unsigned m = __ballot_sync(0xffffffffu, mn[p] > 0);
        if (lane == 0) smask[r*8 + warp] = m;    // chunk key = p/32
    }
    __syncthreads();
    sscan[tid] = __popc(smask[tid]);
    __syncthreads();
    #pragma unroll
    for (int off = 1; off < 256; off <<= 1) {
        int v = (tid >= off) ? sscan[tid - off] : 0;
        __syncthreads();
        sscan[tid] += v;
        __syncthreads();
    }
    if (tid == 255) g_near_cnt[b] = sscan[255];
    #pragma unroll 4
    for (int r = 0; r < 32; r++) {
        int p = r * 256 + tid;
        if (mn[p] > 0) {
            int key = r*8 + warp;
            unsigned m = smask[key];
            int rank = sscan[key] - __popc(m) + __popc(m & ((1u << lane) - 1u));
            float x = pn[p], y = pn[HWN + p], z = pn[2*HWN + p];
            g_nearc[b*HWN + rank] = make_float4(x, y, z, sqnorm_ref(x, y, z));
            g_near_idx[b*HWN + rank] = p;
        }
    }
    __syncthreads();

    // ===== phase B: far (predicate = mask > 0 && cell in range) =====
    const int*   mf  = maskf + b * HWN;
    const float* pff = piff + (size_t)b * 4 * HWN;
    #pragma unroll 4
    for (int r = 0; r < 32; r++) {
        int p = r * 256 + tid;
        bool v = mf[p] > 0;
        if (v) {
            int ix = cell_x(pff[p]), iy = cell_y(pff[HWN + p]);
            v = (ix >= 0 && ix < NXG && iy >= 0 && iy < NYG);
        }
        unsigned m = __ballot_sync(0xffffffffu, v);
        if (lane == 0) smask[r*8 + warp] = m;
    }
    __syncthreads();
    sscan[tid] = __popc(smask[tid]);
    __syncthreads();
    #pragma unroll
    for (int off = 1; off < 256; off <<= 1) {
        int v = (tid >= off) ? sscan[tid - off] : 0;
        __syncthreads();
        sscan[tid] += v;
        __syncthreads();
    }
    if (tid == 255) g_far_cnt[b] = sscan[255];
    #pragma unroll 4
    for (int r = 0; r < 32; r++) {
        int p = r * 256 + tid;
        int key = r*8 + warp;
        unsigned m = smask[key];
        if ((m >> lane) & 1u) {
            int rank = sscan[key] - __popc(m) + __popc(m & ((1u << lane) - 1u));
            g_far_idx[b*HWN + rank] = p;
        }
    }
}

// ---------------------------------------------------------------------------
// K2: zero d_out ∥ transpose ∥ kNN ∥ count, interleaved 1:1 so DRAM-bound
//     zeroing overlaps compute-bound kNN from the first wave.
//     odd bid  -> zero chunk (bid/2) of d_out
//     even bid -> task k = bid/2: [0,2048) kNN, [2048,2112) count,
//                                 [2112,3136) transpose
// ---------------------------------------------------------------------------
__global__ void __launch_bounds__(256) k2_kernel(const float* __restrict__ fv,
                                                 const float* __restrict__ pif_far,
                                                 float* __restrict__ out) {
    int bid = blockIdx.x;
    int tid = threadIdx.x;

    if (bid & 1) {                               // ---- zero d_out ----
        int zc = bid >> 1;                       // 0..4095
        float4* o4 = (float4*)out;
        size_t base = (size_t)zc * 2048 + tid;
        const float4 z = make_float4(0.f, 0.f, 0.f, 0.f);
        #pragma unroll
        for (int i = 0; i < 8; i++)
            o4[base + (size_t)i * 256] = z;
        return;
    }

    int k = bid >> 1;
    if (k >= K2_TASKS) return;

    if (k >= KNN_TASKS + CNT_TASKS) {            // ---- transpose ----
        int idx = k - (KNN_TASKS + CNT_TASKS);
        __shared__ float tile[32][33];
        int b  = idx / ((HWN/32) * (CC/32));
        int r  = idx % ((HWN/32) * (CC/32));
        int c0 = (r / (HWN/32)) * 32;
        int p0 = (r % (HWN/32)) * 32;
        int tx = tid & 31, ty = tid >> 5;        // 32 x 8
        #pragma unroll
        for (int i = ty; i < 32; i += 8)
            tile[i][tx] = fv[((size_t)b*CC + c0 + i) * HWN + p0 + tx];
        __syncthreads();
        #pragma unroll
        for (int i = ty; i < 32; i += 8)
            g_fvT[((size_t)b*HWN + p0 + i) * CC + c0 + tx] = tile[tx][i];
        return;
    }

    if (k >= KNN_TASKS) {                        // ---- counting ----
        int idx = k - KNN_TASKS;                 // 0..63
        int b = idx >> 5;
        int slot = (idx & 31) * 256 + tid;
        if (slot < g_near_cnt[b]) {
            float4 q = g_nearc[b*HWN + slot];
            int ix = cell_x(q.x), iy = cell_y(q.y);
            if (ix >= 0 && ix < NXG && iy >= 0 && iy < NYG)
                atomicAdd(&g_cnt[b*NCELL + iy*NXG + ix], 1.0f);
        }
        if (slot < g_far_cnt[b]) {
            int p = g_far_idx[b*HWN + slot];
            const float* pf = pif_far + (size_t)b * 4 * HWN;
            int ix = cell_x(pf[p]), iy = cell_y(pf[HWN + p]);  // in range by compaction
            atomicAdd(&g_cnt[b*NCELL + iy*NXG + ix], 1.0f);
        }
        return;
    }

    // ---- kNN: k = far-block (5b) | chunk (5b) | batch ----
    __shared__ float4 sh[NCHUNK];
    int fb = k & 31;
    int ch = (k >> 5) & 31;
    int b  = k >> 10;
    int nbase = ch * NCHUNK;
    int ncnt = g_near_cnt[b];
    if (nbase >= ncnt) return;
    if (fb * 256 >= g_far_cnt[b]) return;

    int navail = min(NCHUNK, ncnt - nbase);
    int n8 = (navail + 7) & ~7;                  // pad to multiple of 8
    const float4* src = g_nearc + b*HWN + nbase;
    for (int i = tid; i < n8; i += 256)
        sh[i] = (i < navail) ? src[i] : make_float4(0.f, 0.f, 0.f, 1e30f);
    __syncthreads();

    int slot = fb * 256 + tid;
    if (slot >= g_far_cnt[b]) return;
    int p = g_far_idx[b*HWN + slot];

    const float* pf = pif_far + (size_t)b * 4 * HWN;
    float x = pf[p], y = pf[HWN + p], z = pf[2*HWN + p];
    float fsq = sqnorm_ref(x, y, z);
    float fx2 = 2.0f * x, fy2 = 2.0f * y, fz2 = 2.0f * z;  // exact

    float s0 = POS_INF, s1 = POS_INF, s2 = POS_INF;
    int   i0 = 0, i1 = 0, i2 = 0;

    #pragma unroll 1
    for (int j = 0; j < n8; j += 8) {
        float d[8];
        #pragma unroll
        for (int u = 0; u < 8; u++) {
            float4 q = sh[j + u];
            d[u] = d2_ref(fx2, fy2, fz2, fsq, q.x, q.y, q.z, q.w);
        }
        float m = fminf(fminf(fminf(d[0], d[1]), fminf(d[2], d[3])),
                        fminf(fminf(d[4], d[5]), fminf(d[6], d[7])));
        if (m < s2) {   // rarely taken
            #pragma unroll
            for (int u = 0; u < 8; u++) INS(d[u], nbase + j + u);
        }
    }

    int base = (b*SCH + ch) * HWN + slot;
    g_ps[base] = make_float4(s0, s1, s2, 0.0f);
    g_pi[base] = make_int4(i0, i1, i2, 0);
}

// ---------------------------------------------------------------------------
// K3: fused scatter with pre-divided terms: atomicAdd(out, f / cnt[cell]).
//     blockIdx.z = 0: near points (64 lanes/pt).
//     blockIdx.z = 1: far points — warp-parallel top-3 merge, IDW weights
//     (reference rounding), then 64-lane gather+scatter.
// ---------------------------------------------------------------------------
__global__ void __launch_bounds__(256) scatter_kernel(const float* __restrict__ pif_far,
                                                      float* __restrict__ out) {
    int b = blockIdx.y;
    int local = threadIdx.x >> 6;                // point-in-block 0..3
    int lane64 = threadIdx.x & 63;
    int slot = blockIdx.x * 4 + local;

    if (blockIdx.z == 0) {
        if (slot >= g_near_cnt[b]) return;
        float4 q = g_nearc[b*HWN + slot];
        int ix = cell_x(q.x), iy = cell_y(q.y);
        if (ix < 0 || ix >= NXG || iy < 0 || iy >= NYG) return;
        int cell = iy * NXG + ix;
        int p = g_near_idx[b*HWN + slot];
        float c = g_cnt[b*NCELL + cell];         // >= 1 here
        float f = g_fvT[((size_t)b*HWN + p) * CC + lane64];   // coalesced
        atomicAdd(out + (size_t)b*CC*NCELL + (size_t)lane64*NCELL + cell,
                  __fdiv_rn(f, c));
        return;
    }

    // ---- far path ----
    __shared__ float sw[4][3];
    __shared__ int   si[4][3];
    __shared__ int   scell[4];

    int fcnt = g_far_cnt[b];
    bool active = slot < fcnt;
    int half = lane64 >> 5;                      // warp-half within the point
    int lane = lane64 & 31;                      // chunk id for half 0

    if (active && half == 0) {
        // lane = chunk; load this chunk's sorted top-3 partial (or sentinels)
        int ncnt = g_near_cnt[b];
        float a0 = POS_INF, a1 = POS_INF, a2 = POS_INF;
        int   c0 = IDX_INF,  c1 = IDX_INF,  c2 = IDX_INF;
        if (lane * NCHUNK < ncnt) {
            int base = (b*SCH + lane) * HWN + slot;
            float4 v = g_ps[base];
            int4  iv = g_pi[base];
            a0 = v.x; a1 = v.y; a2 = v.z;
            c0 = iv.x; c1 = iv.y; c2 = iv.z;
        }
        // 3-round warp argmin by (value, then compacted index) — identical to
        // sequential INS order (chunks partition ascending indices; within-chunk
        // triples are index-ordered on equal values).
        float S[3]; int I[3];
        #pragma unroll
        for (int k = 0; k < 3; k++) {
            float bv = a0; int bx = c0;
            #pragma unroll
            for (int off = 16; off; off >>= 1) {
                float ov = __shfl_down_sync(0xffffffffu, bv, off);
                int   ox = __shfl_down_sync(0xffffffffu, bx, off);
                if (ov < bv || (ov == bv && ox < bx)) { bv = ov; bx = ox; }
            }
            bv = __shfl_sync(0xffffffffu, bv, 0);
            bx = __shfl_sync(0xffffffffu, bx, 0);
            S[k] = bv; I[k] = bx;
            if (c0 == bx) {                      // unique index -> unique winner
                a0 = a1; c0 = c1; a1 = a2; c1 = c2;
                a2 = POS_INF; c2 = IDX_INF;
            }
        }
        if (lane == 0) {
            // IDW weights exactly as reference: r = 1/(d+1e-8); w = r/((r0+r1)+r2)
            float r0 = __fdiv_rn(1.0f, __fadd_rn(S[0], 1e-8f));
            float r1 = __fdiv_rn(1.0f, __fadd_rn(S[1], 1e-8f));
            float r2 = __fdiv_rn(1.0f, __fadd_rn(S[2], 1e-8f));
            float rs = __fadd_rn(__fadd_rn(r0, r1), r2);
            sw[local][0] = __fdiv_rn(r0, rs);
            sw[local][1] = __fdiv_rn(r1, rs);
            sw[local][2] = __fdiv_rn(r2, rs);
            si[local][0] = g_near_idx[b*HWN + I[0]];
            si[local][1] = g_near_idx[b*HWN + I[1]];
            si[local][2] = g_near_idx[b*HWN + I[2]];
            int p = g_far_idx[b*HWN + slot];
            const float* pf = pif_far + (size_t)b * 4 * HWN;
            int ix = cell_x(pf[p]), iy = cell_y(pf[HWN + p]);  // in range by compaction
            scell[local] = iy * NXG + ix;
        }
    }
    __syncthreads();
    if (!active) return;

    float w0 = sw[local][0], w1 = sw[local][1], w2 = sw[local][2];
    int   j0 = si[local][0], j1 = si[local][1], j2 = si[local][2];
    int cell = scell[local];
    float c = g_cnt[b*NCELL + cell];             // >= 1 here
    const float* fT = g_fvT + (size_t)b*HWN*CC;
    // einsum order: (w0*g0 + w1*g1) + w2*g2, no fma
    float f = __fadd_rn(__fadd_rn(__fmul_rn(w0, fT[(size_t)j0*CC + lane64]),
                                  __fmul_rn(w1, fT[(size_t)j1*CC + lane64])),
                        __fmul_rn(w2, fT[(size_t)j2*CC + lane64]));
    atomicAdd(out + (size_t)b*CC*NCELL + (size_t)lane64*NCELL + cell,
              __fdiv_rn(f, c));
}

extern "C" void kernel_launch(void* const* d_in, const int* in_sizes, int n_in,
                              void* d_out, int out_size) {
    const float* fv    = (const float*)d_in[0];   // (B,C,H,W)
    const float* pif   = (const float*)d_in[1];   // (B,4,H,W)
    const int*   mask  = (const int*)  d_in[2];   // (B,H,W)
    const float* piff  = (const float*)d_in[3];   // (B,4,H,W)
    const int*   maskf = (const int*)  d_in[4];   // (B,H,W)
    float* out = (float*)d_out;                   // (B,C,NY,NX)

    k1_kernel<<<K1_BLKS, 256>>>(pif, mask, piff, maskf);

    k2_kernel<<<K2_BLKS, 256>>>(fv, piff, out);

    scatter_kernel<<<dim3(HWN/4, BB, 2), 256>>>(piff, out);
}